// round 7
// baseline (speedup 1.0000x reference)
#include <cuda_runtime.h>
#include <cuda_bf16.h>
#include <math.h>
#include <stdint.h>

#define Bn   8
#define Nn   16384
#define Cn   128
#define OUTn 256
#define En   262144

// ---- scratch (static device globals; no allocation allowed) ----
__device__ __align__(16) int g_deg[Nn];
__device__ int   g_off[Nn + 1];
__device__ int   g_cur[Nn];
__device__ int   g_csr[En];
__device__ int   g_is64;
__device__ int   g_done[Bn];
__device__ __nv_bfloat16 g_ahi[(size_t)Bn * Nn * Cn];   // 32 MB aggr hi
__device__ __nv_bfloat16 g_alo[(size_t)Bn * Nn * Cn];   // 32 MB aggr lo
__device__ __nv_bfloat16 g_wbh[(size_t)OUTn * Cn];      // W^T hi [N][K]
__device__ __nv_bfloat16 g_wbl[(size_t)OUTn * Cn];      // W^T lo [N][K]

__device__ __forceinline__ uint32_t smem_u32(const void* p) {
    return (uint32_t)__cvta_generic_to_shared(p);
}
#define CP_ASYNC16(dst_u32, src_ptr) \
    asm volatile("cp.async.cg.shared.global [%0], [%1], 16;" :: "r"(dst_u32), "l"(src_ptr))
#define CP_COMMIT() asm volatile("cp.async.commit_group;" ::: "memory")
#define CP_WAIT(n)  asm volatile("cp.async.wait_group %0;" :: "n"(n) : "memory")

// ============================================================
// detect dtype (int64 vs int32) + init arrays, one kernel
// ============================================================
__global__ void detinit_kernel(const unsigned int* __restrict__ ei_raw) {
    int i = blockIdx.x * blockDim.x + threadIdx.x;
    if (i < Nn) { g_deg[i] = 0; g_cur[i] = 0; }
    if (i < Bn) g_done[i] = 0;
    if (i == 0) {
        int hi_zero = 0;
        for (int k = 0; k < 256; k++)
            if (ei_raw[2 * k + 1] == 0) hi_zero++;
        g_is64 = (hi_zero >= 250) ? 1 : 0;
    }
}

__device__ __forceinline__ int load_idx(const void* ei, int pos, int is64) {
    if (is64) return (int)((const long long*)ei)[pos];
    return ((const int*)ei)[pos];
}

// ============================================================
// CSR build
// ============================================================
__global__ void count_kernel(const void* __restrict__ ei) {
    int e = blockIdx.x * blockDim.x + threadIdx.x;
    int is64 = g_is64;
    if (e < En) {
        int r = load_idx(ei, e, is64);
        if ((unsigned)r < Nn) atomicAdd(&g_deg[r], 1);
    }
}

__global__ void __launch_bounds__(1024) scan_kernel() {
    __shared__ int wsum[32];
    int t = threadIdx.x, lane = t & 31, wid = t >> 5;
    int4 v0 = ((const int4*)g_deg)[t * 4 + 0];
    int4 v1 = ((const int4*)g_deg)[t * 4 + 1];
    int4 v2 = ((const int4*)g_deg)[t * 4 + 2];
    int4 v3 = ((const int4*)g_deg)[t * 4 + 3];
    int vals[16] = {v0.x, v0.y, v0.z, v0.w, v1.x, v1.y, v1.z, v1.w,
                    v2.x, v2.y, v2.z, v2.w, v3.x, v3.y, v3.z, v3.w};
    int tot = 0;
#pragma unroll
    for (int i = 0; i < 16; i++) tot += vals[i];
    int inc = tot;
#pragma unroll
    for (int off = 1; off < 32; off <<= 1) {
        int n = __shfl_up_sync(0xFFFFFFFFu, inc, off);
        if (lane >= off) inc += n;
    }
    if (lane == 31) wsum[wid] = inc;
    __syncthreads();
    if (wid == 0) {
        int w = wsum[lane];
        int wi = w;
#pragma unroll
        for (int off = 1; off < 32; off <<= 1) {
            int n = __shfl_up_sync(0xFFFFFFFFu, wi, off);
            if (lane >= off) wi += n;
        }
        wsum[lane] = wi - w;
    }
    __syncthreads();
    int run = wsum[wid] + (inc - tot);
#pragma unroll
    for (int i = 0; i < 16; i++) { g_off[t * 16 + i] = run; run += vals[i]; }
    if (t == 1023) g_off[Nn] = run;
}

__global__ void scatter_kernel(const void* __restrict__ ei) {
    int e = blockIdx.x * blockDim.x + threadIdx.x;
    int is64 = g_is64;
    if (e < En) {
        int r = load_idx(ei, e, is64);
        int c = load_idx(ei, En + e, is64);
        if ((unsigned)r < Nn && (unsigned)c < Nn) {
            int p = atomicAdd(&g_cur[r], 1);
            g_csr[g_off[r] + p] = c;
        }
    }
}

// ============================================================
// W^T + bf16 hi/lo split:  W[K=128][N=256] -> Wt[N][K]
// ============================================================
__global__ void wt_split_kernel(const float* __restrict__ W) {
    int idx = blockIdx.x * blockDim.x + threadIdx.x;   // 32768
    int k = idx >> 8;
    int n = idx & 255;
    float a = W[idx];
    __nv_bfloat16 h = __float2bfloat16_rn(a);
    __nv_bfloat16 l = __float2bfloat16_rn(a - __bfloat162float(h));
    g_wbh[(size_t)n * Cn + k] = h;
    g_wbl[(size_t)n * Cn + k] = l;
}

// ============================================================
// FUSED aggregate + GEMM, one launch.
// bid layout per batch b: [256 agg blocks (64 nodes each)][128 gemm blocks].
// Agg: gather-max - x -> bf16 hi/lo -> g_ahi/g_alo, then bump g_done[b].
// Gemm: spin on g_done[b], then bf16x3 mma.sync GEMM + bias + exact GELU.
// ============================================================
#define MMA_BF16(d, a, b) \
    asm volatile("mma.sync.aligned.m16n8k16.row.col.f32.bf16.bf16.f32 " \
        "{%0,%1,%2,%3}, {%4,%5,%6,%7}, {%8,%9}, {%0,%1,%2,%3};" \
        : "+f"((d)[0]), "+f"((d)[1]), "+f"((d)[2]), "+f"((d)[3]) \
        : "r"((a)[0]), "r"((a)[1]), "r"((a)[2]), "r"((a)[3]), \
          "r"((b)[0]), "r"((b)[1]))

#define LDK   72
#define A_ST  (128 * LDK)
#define B_ST  (256 * LDK)
#define OFF_AH 0
#define OFF_AL (2 * A_ST)
#define OFF_BH (4 * A_ST)
#define OFF_BL (4 * A_ST + 2 * B_ST)
#define GEMM_SMEM ((4 * A_ST + 4 * B_ST) * 2)   // 221184 bytes

#define AGG_BLKS  256     // per batch
#define GEMM_BLKS 128     // per batch
#define SEG       (AGG_BLKS + GEMM_BLKS)

__device__ __forceinline__ float gelu_exact(float v) {
    return 0.5f * v * (1.0f + erff(v * 0.70710678118654752f));
}
__device__ __forceinline__ void fmax4(float4& m, float4 v) {
    m.x = fmaxf(m.x, v.x); m.y = fmaxf(m.y, v.y);
    m.z = fmaxf(m.z, v.z); m.w = fmaxf(m.w, v.w);
}

__global__ void __launch_bounds__(512, 1) fused_kernel(const float* __restrict__ x,
                                                       const float* __restrict__ bias,
                                                       float* __restrict__ out) {
    extern __shared__ __align__(16) __nv_bfloat16 smem[];
    const int bid = blockIdx.x;
    const int b = bid / SEG;
    const int r = bid % SEG;
    const int tid = threadIdx.x;

    if (r < AGG_BLKS) {
        // ---------------- aggregate block: 64 nodes, 8 threads/node ----------------
        const int node = r * 64 + (tid >> 3);
        const int ch = (tid & 7) * 16;
        const int s = g_off[node];
        const int e = g_off[node + 1];
        const float* xb = x + (size_t)b * Nn * Cn;

        float4 m[4];
        const float NEG = -3.0e38f;
#pragma unroll
        for (int q = 0; q < 4; q++) m[q] = make_float4(NEG, NEG, NEG, NEG);

        int k = s;
        for (; k + 2 <= e; k += 2) {
            const float4* p0 = (const float4*)(xb + (size_t)g_csr[k] * Cn + ch);
            const float4* p1 = (const float4*)(xb + (size_t)g_csr[k + 1] * Cn + ch);
            float4 a0 = p0[0], a1 = p0[1], a2 = p0[2], a3 = p0[3];
            float4 c0 = p1[0], c1 = p1[1], c2 = p1[2], c3 = p1[3];
            fmax4(m[0], a0); fmax4(m[1], a1); fmax4(m[2], a2); fmax4(m[3], a3);
            fmax4(m[0], c0); fmax4(m[1], c1); fmax4(m[2], c2); fmax4(m[3], c3);
        }
        if (k < e) {
            const float4* p0 = (const float4*)(xb + (size_t)g_csr[k] * Cn + ch);
            fmax4(m[0], p0[0]); fmax4(m[1], p0[1]); fmax4(m[2], p0[2]); fmax4(m[3], p0[3]);
        }
        if (s == e) {
#pragma unroll
            for (int q = 0; q < 4; q++) m[q] = make_float4(0.f, 0.f, 0.f, 0.f);
        }

        const float* xr = xb + (size_t)node * Cn + ch;
        float v[16];
#pragma unroll
        for (int q = 0; q < 4; q++) {
            float4 xv = ((const float4*)xr)[q];
            v[q * 4 + 0] = (&m[q].x)[0] - xv.x;
            v[q * 4 + 1] = (&m[q].x)[1] - xv.y;
            v[q * 4 + 2] = (&m[q].x)[2] - xv.z;
            v[q * 4 + 3] = (&m[q].x)[3] - xv.w;
        }
        uint32_t ph[8], pl[8];
#pragma unroll
        for (int q = 0; q < 8; q++) {
            float v0 = v[q * 2], v1 = v[q * 2 + 1];
            __nv_bfloat16 h0 = __float2bfloat16_rn(v0);
            __nv_bfloat16 h1 = __float2bfloat16_rn(v1);
            float l0 = v0 - __bfloat162float(h0);
            float l1 = v1 - __bfloat162float(h1);
            __nv_bfloat162 hh = __halves2bfloat162(h0, h1);
            __nv_bfloat162 ll = __halves2bfloat162(__float2bfloat16_rn(l0), __float2bfloat16_rn(l1));
            ph[q] = *(uint32_t*)&hh;
            pl[q] = *(uint32_t*)&ll;
        }
        size_t base = ((size_t)b * Nn + node) * Cn + ch;
        *(uint4*)&g_ahi[base]     = make_uint4(ph[0], ph[1], ph[2], ph[3]);
        *(uint4*)&g_ahi[base + 8] = make_uint4(ph[4], ph[5], ph[6], ph[7]);
        *(uint4*)&g_alo[base]     = make_uint4(pl[0], pl[1], pl[2], pl[3]);
        *(uint4*)&g_alo[base + 8] = make_uint4(pl[4], pl[5], pl[6], pl[7]);

        __threadfence();
        __syncthreads();
        if (tid == 0) atomicAdd(&g_done[b], 1);
        return;
    }

    // ---------------- gemm block ----------------
    {
        // wait for this batch's aggregation
        if (tid == 0) {
            while (atomicAdd(&g_done[b], 0) < AGG_BLKS) __nanosleep(200);
            __threadfence();
        }
        __syncthreads();
    }

    const int wid = tid >> 5;
    const int lane = tid & 31;
    const size_t m0 = (size_t)b * Nn * 1 * 1 + (size_t)(r - AGG_BLKS) * 128;
    const int warp_m = wid & 3;
    const int warp_n = wid >> 2;

#pragma unroll
    for (int s = 0; s < 2; s++) {
        const int ks = s * 64;
#pragma unroll
        for (int it = 0; it < 2; it++) {
            int q = it * 512 + tid;
            int rr = q >> 3;
            int c8 = (q & 7) * 8;
            uint32_t dh = smem_u32(&smem[OFF_AH + s * A_ST + rr * LDK + c8]);
            uint32_t dl = smem_u32(&smem[OFF_AL + s * A_ST + rr * LDK + c8]);
            CP_ASYNC16(dh, &g_ahi[(m0 + rr) * Cn + ks + c8]);
            CP_ASYNC16(dl, &g_alo[(m0 + rr) * Cn + ks + c8]);
        }
#pragma unroll
        for (int it = 0; it < 4; it++) {
            int q = it * 512 + tid;
            int n = q >> 3;
            int c8 = (q & 7) * 8;
            uint32_t dh = smem_u32(&smem[OFF_BH + s * B_ST + n * LDK + c8]);
            uint32_t dl = smem_u32(&smem[OFF_BL + s * B_ST + n * LDK + c8]);
            CP_ASYNC16(dh, &g_wbh[(size_t)n * Cn + ks + c8]);
            CP_ASYNC16(dl, &g_wbl[(size_t)n * Cn + ks + c8]);
        }
        CP_COMMIT();
    }

    const int gr = lane >> 2;
    const int tg = lane & 3;

    float acc[2][8][4];
#pragma unroll
    for (int mf = 0; mf < 2; mf++)
#pragma unroll
        for (int nf = 0; nf < 8; nf++)
#pragma unroll
            for (int q = 0; q < 4; q++) acc[mf][nf][q] = 0.0f;

#pragma unroll
    for (int s = 0; s < 2; s++) {
        if (s == 0) { CP_WAIT(1); } else { CP_WAIT(0); }
        __syncthreads();
        const __nv_bfloat16* Ah = smem + OFF_AH + s * A_ST;
        const __nv_bfloat16* Al = smem + OFF_AL + s * A_ST;
        const __nv_bfloat16* Bh = smem + OFF_BH + s * B_ST;
        const __nv_bfloat16* Bl = smem + OFF_BL + s * B_ST;

#pragma unroll
        for (int kc = 0; kc < 4; kc++) {
            const int kb = kc * 16 + tg * 2;
            uint32_t ah[2][4], al[2][4];
#pragma unroll
            for (int mf = 0; mf < 2; mf++) {
                int m = warp_m * 32 + mf * 16 + gr;
                ah[mf][0] = *(const uint32_t*)&Ah[m * LDK + kb];
                ah[mf][1] = *(const uint32_t*)&Ah[(m + 8) * LDK + kb];
                ah[mf][2] = *(const uint32_t*)&Ah[m * LDK + kb + 8];
                ah[mf][3] = *(const uint32_t*)&Ah[(m + 8) * LDK + kb + 8];
                al[mf][0] = *(const uint32_t*)&Al[m * LDK + kb];
                al[mf][1] = *(const uint32_t*)&Al[(m + 8) * LDK + kb];
                al[mf][2] = *(const uint32_t*)&Al[m * LDK + kb + 8];
                al[mf][3] = *(const uint32_t*)&Al[(m + 8) * LDK + kb + 8];
            }
#pragma unroll
            for (int nf = 0; nf < 8; nf++) {
                int n = warp_n * 64 + nf * 8 + gr;
                uint32_t bh[2], bl[2];
                bh[0] = *(const uint32_t*)&Bh[n * LDK + kb];
                bh[1] = *(const uint32_t*)&Bh[n * LDK + kb + 8];
                bl[0] = *(const uint32_t*)&Bl[n * LDK + kb];
                bl[1] = *(const uint32_t*)&Bl[n * LDK + kb + 8];
#pragma unroll
                for (int mf = 0; mf < 2; mf++) {
                    MMA_BF16(acc[mf][nf], ah[mf], bh);
                    MMA_BF16(acc[mf][nf], al[mf], bh);
                    MMA_BF16(acc[mf][nf], ah[mf], bl);
                }
            }
        }
        if (s == 0) __syncthreads();
    }

#pragma unroll
    for (int nf = 0; nf < 8; nf++) {
        int col = warp_n * 64 + nf * 8 + tg * 2;
        float b0 = __ldg(&bias[col]), b1 = __ldg(&bias[col + 1]);
#pragma unroll
        for (int mf = 0; mf < 2; mf++) {
            size_t row = m0 + warp_m * 32 + mf * 16 + gr;
            float2 v0, v1;
            v0.x = gelu_exact(acc[mf][nf][0] + b0);
            v0.y = gelu_exact(acc[mf][nf][1] + b1);
            v1.x = gelu_exact(acc[mf][nf][2] + b0);
            v1.y = gelu_exact(acc[mf][nf][3] + b1);
            *(float2*)&out[row * OUTn + col]       = v0;
            *(float2*)&out[(row + 8) * OUTn + col] = v1;
        }
    }
}

// ============================================================
extern "C" void kernel_launch(void* const* d_in, const int* in_sizes, int n_in,
                              void* d_out, int out_size) {
    const float* x    = (const float*)d_in[0];
    const void*  ei   = d_in[1];
    const float* Wm   = (const float*)d_in[2];
    const float* bias = (const float*)d_in[3];
    float*       out  = (float*)d_out;

    cudaFuncSetAttribute(fused_kernel, cudaFuncAttributeMaxDynamicSharedMemorySize, GEMM_SMEM);

    detinit_kernel<<<(Nn + 255) / 256, 256>>>((const unsigned int*)ei);
    count_kernel<<<En / 256, 256>>>(ei);
    scan_kernel<<<1, 1024>>>();
    scatter_kernel<<<En / 256, 256>>>(ei);
    wt_split_kernel<<<(Cn * OUTn) / 256, 256>>>(Wm);
    fused_kernel<<<Bn * SEG, 512, GEMM_SMEM>>>(x, bias, out);
}

// round 8
// speedup vs baseline: 1.7273x; 1.7273x over previous
#include <cuda_runtime.h>
#include <cuda_fp16.h>
#include <math.h>
#include <stdint.h>

#define Bn   8
#define Nn   16384
#define Cn   128
#define OUTn 256
#define En   262144

// ---- scratch (static device globals; no allocation allowed) ----
__device__ __align__(16) int g_deg[Nn];
__device__ int   g_off[Nn + 1];
__device__ int   g_cur[Nn];
__device__ int   g_csr[En];
__device__ int   g_is64;
__device__ __half g_ahi[(size_t)Bn * Nn * Cn];   // 32 MB aggr hi (fp16)
__device__ __half g_alo[(size_t)Bn * Nn * Cn];   // 32 MB aggr lo (fp16)
__device__ __half g_wbh[(size_t)OUTn * Cn];      // W^T fp16 [N][K]

__device__ __forceinline__ uint32_t smem_u32(const void* p) {
    return (uint32_t)__cvta_generic_to_shared(p);
}
#define CP_ASYNC16(dst_u32, src_ptr) \
    asm volatile("cp.async.cg.shared.global [%0], [%1], 16;" :: "r"(dst_u32), "l"(src_ptr))
#define CP_COMMIT() asm volatile("cp.async.commit_group;" ::: "memory")
#define CP_WAIT(n)  asm volatile("cp.async.wait_group %0;" :: "n"(n) : "memory")

// ============================================================
// detect dtype + init arrays + W^T fp16 convert, one kernel
// ============================================================
__global__ void detinit_kernel(const unsigned int* __restrict__ ei_raw,
                               const float* __restrict__ W) {
    int i = blockIdx.x * blockDim.x + threadIdx.x;   // 32768 threads
    if (i < Nn) { g_deg[i] = 0; g_cur[i] = 0; }
    if (i < Cn * OUTn) {
        int k = i >> 8;
        int n = i & 255;
        g_wbh[(size_t)n * Cn + k] = __float2half_rn(W[i]);
    }
    if (i == 0) {
        int hi_zero = 0;
        for (int q = 0; q < 256; q++)
            if (ei_raw[2 * q + 1] == 0) hi_zero++;
        g_is64 = (hi_zero >= 250) ? 1 : 0;
    }
}

__device__ __forceinline__ int load_idx(const void* ei, int pos, int is64) {
    if (is64) return (int)((const long long*)ei)[pos];
    return ((const int*)ei)[pos];
}

// ============================================================
// CSR build
// ============================================================
__global__ void count_kernel(const void* __restrict__ ei) {
    int e = blockIdx.x * blockDim.x + threadIdx.x;
    int is64 = g_is64;
    if (e < En) {
        int r = load_idx(ei, e, is64);
        if ((unsigned)r < Nn) atomicAdd(&g_deg[r], 1);
    }
}

__global__ void __launch_bounds__(1024) scan_kernel() {
    __shared__ int wsum[32];
    int t = threadIdx.x, lane = t & 31, wid = t >> 5;
    int4 v0 = ((const int4*)g_deg)[t * 4 + 0];
    int4 v1 = ((const int4*)g_deg)[t * 4 + 1];
    int4 v2 = ((const int4*)g_deg)[t * 4 + 2];
    int4 v3 = ((const int4*)g_deg)[t * 4 + 3];
    int vals[16] = {v0.x, v0.y, v0.z, v0.w, v1.x, v1.y, v1.z, v1.w,
                    v2.x, v2.y, v2.z, v2.w, v3.x, v3.y, v3.z, v3.w};
    int tot = 0;
#pragma unroll
    for (int i = 0; i < 16; i++) tot += vals[i];
    int inc = tot;
#pragma unroll
    for (int off = 1; off < 32; off <<= 1) {
        int n = __shfl_up_sync(0xFFFFFFFFu, inc, off);
        if (lane >= off) inc += n;
    }
    if (lane == 31) wsum[wid] = inc;
    __syncthreads();
    if (wid == 0) {
        int w = wsum[lane];
        int wi = w;
#pragma unroll
        for (int off = 1; off < 32; off <<= 1) {
            int n = __shfl_up_sync(0xFFFFFFFFu, wi, off);
            if (lane >= off) wi += n;
        }
        wsum[lane] = wi - w;
    }
    __syncthreads();
    int run = wsum[wid] + (inc - tot);
#pragma unroll
    for (int i = 0; i < 16; i++) { g_off[t * 16 + i] = run; run += vals[i]; }
    if (t == 1023) g_off[Nn] = run;
}

__global__ void scatter_kernel(const void* __restrict__ ei) {
    int e = blockIdx.x * blockDim.x + threadIdx.x;
    int is64 = g_is64;
    if (e < En) {
        int r = load_idx(ei, e, is64);
        int c = load_idx(ei, En + e, is64);
        if ((unsigned)r < Nn && (unsigned)c < Nn) {
            int p = atomicAdd(&g_cur[r], 1);
            g_csr[g_off[r] + p] = c;
        }
    }
}

// ============================================================
// Aggregation: per node, all 8 batches, gather-max - x, fp16 hi/lo split
// ============================================================
__global__ void __launch_bounds__(128) aggregate_kernel(const float* __restrict__ x) {
    const int i = blockIdx.x;
    const int c = threadIdx.x;
    const int s = g_off[i];
    const int e = g_off[i + 1];

    float m[Bn];
#pragma unroll
    for (int b = 0; b < Bn; b++) m[b] = -INFINITY;

    int k = s;
    for (; k + 4 <= e; k += 4) {
        int j0 = g_csr[k + 0], j1 = g_csr[k + 1], j2 = g_csr[k + 2], j3 = g_csr[k + 3];
        size_t o0 = (size_t)j0 * Cn + c, o1 = (size_t)j1 * Cn + c;
        size_t o2 = (size_t)j2 * Cn + c, o3 = (size_t)j3 * Cn + c;
#pragma unroll
        for (int b = 0; b < Bn; b++) {
            size_t xb = (size_t)b * Nn * Cn;
            float v0 = __ldg(&x[xb + o0]);
            float v1 = __ldg(&x[xb + o1]);
            float v2 = __ldg(&x[xb + o2]);
            float v3 = __ldg(&x[xb + o3]);
            m[b] = fmaxf(m[b], fmaxf(fmaxf(v0, v1), fmaxf(v2, v3)));
        }
    }
    for (; k < e; k++) {
        int j = g_csr[k];
        size_t o = (size_t)j * Cn + c;
#pragma unroll
        for (int b = 0; b < Bn; b++)
            m[b] = fmaxf(m[b], __ldg(&x[(size_t)b * Nn * Cn + o]));
    }

    const bool none = (s == e);
    const size_t obase = (size_t)i * Cn + c;
#pragma unroll
    for (int b = 0; b < Bn; b++) {
        size_t idx = (size_t)b * Nn * Cn + obase;
        float v = (none ? 0.0f : m[b]) - x[idx];
        __half h = __float2half_rn(v);
        __half l = __float2half_rn(v - __half2float(h));
        g_ahi[idx] = h;
        g_alo[idx] = l;
    }
}

// ============================================================
// GEMM via mma.sync fp16x2: (131072 x 128) @ (128 x 256) + bias + exact GELU
// out = (Ah + Al) @ Wh  (W residual term dropped; rel_err ~2e-4)
// CTA tile 128x256, 16 warps, warp tile 32x64.
// 2-stage cp.async pipeline over K halves (64 each).
// ============================================================
#define MMA_F16(d, a, b) \
    asm volatile("mma.sync.aligned.m16n8k16.row.col.f32.f16.f16.f32 " \
        "{%0,%1,%2,%3}, {%4,%5,%6,%7}, {%8,%9}, {%0,%1,%2,%3};" \
        : "+f"((d)[0]), "+f"((d)[1]), "+f"((d)[2]), "+f"((d)[3]) \
        : "r"((a)[0]), "r"((a)[1]), "r"((a)[2]), "r"((a)[3]), \
          "r"((b)[0]), "r"((b)[1]))

#define LDK   72                      // 64 + 8 pad (fp16)
#define A_ST  (128 * LDK)             // 9216 elements per (stage, part)
#define B_ST  (256 * LDK)             // 18432
#define OFF_AH 0
#define OFF_AL (2 * A_ST)
#define OFF_BH (4 * A_ST)
#define GEMM_SMEM ((4 * A_ST + 2 * B_ST) * 2)   // 147456 bytes

__device__ __forceinline__ float gelu_exact(float v) {
    return 0.5f * v * (1.0f + erff(v * 0.70710678118654752f));
}

__global__ void __launch_bounds__(512, 1) gemm_mma_kernel(const float* __restrict__ bias,
                                                          float* __restrict__ out) {
    extern __shared__ __align__(16) __half smem[];
    const int tid = threadIdx.x;
    const int wid = tid >> 5;
    const int lane = tid & 31;
    const size_t m0 = (size_t)blockIdx.x * 128;
    const int warp_m = wid & 3;    // 4 x 32 rows
    const int warp_n = wid >> 2;   // 4 x 64 cols

    // ---- async load both K-stages ----
#pragma unroll
    for (int s = 0; s < 2; s++) {
        const int ks = s * 64;
        // A hi/lo: 1024 16B-chunks each
#pragma unroll
        for (int it = 0; it < 2; it++) {
            int q = it * 512 + tid;
            int r = q >> 3;
            int c8 = (q & 7) * 8;
            uint32_t dh = smem_u32(&smem[OFF_AH + s * A_ST + r * LDK + c8]);
            uint32_t dl = smem_u32(&smem[OFF_AL + s * A_ST + r * LDK + c8]);
            CP_ASYNC16(dh, &g_ahi[(m0 + r) * Cn + ks + c8]);
            CP_ASYNC16(dl, &g_alo[(m0 + r) * Cn + ks + c8]);
        }
        // B hi: 2048 16B-chunks
#pragma unroll
        for (int it = 0; it < 4; it++) {
            int q = it * 512 + tid;
            int n = q >> 3;
            int c8 = (q & 7) * 8;
            uint32_t dh = smem_u32(&smem[OFF_BH + s * B_ST + n * LDK + c8]);
            CP_ASYNC16(dh, &g_wbh[(size_t)n * Cn + ks + c8]);
        }
        CP_COMMIT();
    }

    const int gr = lane >> 2;       // group row 0..7
    const int tg = lane & 3;        // thread in group

    float acc[2][8][4];
#pragma unroll
    for (int mf = 0; mf < 2; mf++)
#pragma unroll
        for (int nf = 0; nf < 8; nf++)
#pragma unroll
            for (int q = 0; q < 4; q++) acc[mf][nf][q] = 0.0f;

#pragma unroll
    for (int s = 0; s < 2; s++) {
        if (s == 0) { CP_WAIT(1); } else { CP_WAIT(0); }
        __syncthreads();
        const __half* Ah = smem + OFF_AH + s * A_ST;
        const __half* Al = smem + OFF_AL + s * A_ST;
        const __half* Bh = smem + OFF_BH + s * B_ST;

#pragma unroll
        for (int kc = 0; kc < 4; kc++) {
            const int kb = kc * 16 + tg * 2;
            uint32_t ah[2][4], al[2][4];
#pragma unroll
            for (int mf = 0; mf < 2; mf++) {
                int m = warp_m * 32 + mf * 16 + gr;
                ah[mf][0] = *(const uint32_t*)&Ah[m * LDK + kb];
                ah[mf][1] = *(const uint32_t*)&Ah[(m + 8) * LDK + kb];
                ah[mf][2] = *(const uint32_t*)&Ah[m * LDK + kb + 8];
                ah[mf][3] = *(const uint32_t*)&Ah[(m + 8) * LDK + kb + 8];
                al[mf][0] = *(const uint32_t*)&Al[m * LDK + kb];
                al[mf][1] = *(const uint32_t*)&Al[(m + 8) * LDK + kb];
                al[mf][2] = *(const uint32_t*)&Al[m * LDK + kb + 8];
                al[mf][3] = *(const uint32_t*)&Al[(m + 8) * LDK + kb + 8];
            }
#pragma unroll
            for (int nf = 0; nf < 8; nf++) {
                int n = warp_n * 64 + nf * 8 + gr;
                uint32_t bh[2];
                bh[0] = *(const uint32_t*)&Bh[n * LDK + kb];
                bh[1] = *(const uint32_t*)&Bh[n * LDK + kb + 8];
#pragma unroll
                for (int mf = 0; mf < 2; mf++) {
                    MMA_F16(acc[mf][nf], ah[mf], bh);
                    MMA_F16(acc[mf][nf], al[mf], bh);
                }
            }
        }
        if (s == 0) __syncthreads();
    }

    // ---- epilogue: bias + exact GELU, direct float2 stores ----
#pragma unroll
    for (int nf = 0; nf < 8; nf++) {
        int col = warp_n * 64 + nf * 8 + tg * 2;
        float b0 = __ldg(&bias[col]), b1 = __ldg(&bias[col + 1]);
#pragma unroll
        for (int mf = 0; mf < 2; mf++) {
            size_t row = m0 + warp_m * 32 + mf * 16 + gr;
            float2 v0, v1;
            v0.x = gelu_exact(acc[mf][nf][0] + b0);
            v0.y = gelu_exact(acc[mf][nf][1] + b1);
            v1.x = gelu_exact(acc[mf][nf][2] + b0);
            v1.y = gelu_exact(acc[mf][nf][3] + b1);
            *(float2*)&out[row * OUTn + col]       = v0;
            *(float2*)&out[(row + 8) * OUTn + col] = v1;
        }
    }
}

// ============================================================
extern "C" void kernel_launch(void* const* d_in, const int* in_sizes, int n_in,
                              void* d_out, int out_size) {
    const float* x    = (const float*)d_in[0];
    const void*  ei   = d_in[1];
    const float* Wm   = (const float*)d_in[2];
    const float* bias = (const float*)d_in[3];
    float*       out  = (float*)d_out;

    cudaFuncSetAttribute(gemm_mma_kernel, cudaFuncAttributeMaxDynamicSharedMemorySize, GEMM_SMEM);

    detinit_kernel<<<(Cn * OUTn) / 256, 256>>>((const unsigned int*)ei, Wm);
    count_kernel<<<En / 256, 256>>>(ei);
    scan_kernel<<<1, 1024>>>();
    scatter_kernel<<<En / 256, 256>>>(ei);
    aggregate_kernel<<<Nn, 128>>>(x);
    gemm_mma_kernel<<<(Bn * Nn) / 128, 512, GEMM_SMEM>>>(bias, out);
}

// round 9
// speedup vs baseline: 1.9347x; 1.1201x over previous
#include <cuda_runtime.h>
#include <cuda_fp16.h>
#include <math.h>
#include <stdint.h>

#define Bn   8
#define Nn   16384
#define Cn   128
#define OUTn 256
#define En   262144

// ---- scratch (static device globals; no allocation allowed) ----
__device__ __align__(16) int g_deg[Nn];
__device__ int   g_off[Nn + 1];
__device__ int   g_cur[Nn];
__device__ int   g_csr[En];
__device__ int   g_is64;
__device__ __half g_ahi[(size_t)Bn * Nn * Cn];   // 32 MB aggr (fp16)
__device__ __half g_wbh[(size_t)OUTn * Cn];      // W^T fp16 [N][K]

__device__ __forceinline__ uint32_t smem_u32(const void* p) {
    return (uint32_t)__cvta_generic_to_shared(p);
}
#define CP_ASYNC16(dst_u32, src_ptr) \
    asm volatile("cp.async.cg.shared.global [%0], [%1], 16;" :: "r"(dst_u32), "l"(src_ptr))
#define CP_COMMIT() asm volatile("cp.async.commit_group;" ::: "memory")
#define CP_WAIT(n)  asm volatile("cp.async.wait_group %0;" :: "n"(n) : "memory")

// ============================================================
// detect dtype + init arrays + W^T fp16 convert, one kernel
// ============================================================
__global__ void detinit_kernel(const unsigned int* __restrict__ ei_raw,
                               const float* __restrict__ W) {
    int i = blockIdx.x * blockDim.x + threadIdx.x;   // 32768 threads
    if (i < Nn) { g_deg[i] = 0; g_cur[i] = 0; }
    if (i < Cn * OUTn) {
        int k = i >> 8;
        int n = i & 255;
        g_wbh[(size_t)n * Cn + k] = __float2half_rn(W[i]);
    }
    if (i == 0) {
        int hi_zero = 0;
        for (int q = 0; q < 256; q++)
            if (ei_raw[2 * q + 1] == 0) hi_zero++;
        g_is64 = (hi_zero >= 250) ? 1 : 0;
    }
}

__device__ __forceinline__ int load_idx(const void* ei, int pos, int is64) {
    if (is64) return (int)((const long long*)ei)[pos];
    return ((const int*)ei)[pos];
}

// ============================================================
// CSR build
// ============================================================
__global__ void count_kernel(const void* __restrict__ ei) {
    int e = blockIdx.x * blockDim.x + threadIdx.x;
    int is64 = g_is64;
    if (e < En) {
        int r = load_idx(ei, e, is64);
        if ((unsigned)r < Nn) atomicAdd(&g_deg[r], 1);
    }
}

__global__ void __launch_bounds__(1024) scan_kernel() {
    __shared__ int wsum[32];
    int t = threadIdx.x, lane = t & 31, wid = t >> 5;
    int4 v0 = ((const int4*)g_deg)[t * 4 + 0];
    int4 v1 = ((const int4*)g_deg)[t * 4 + 1];
    int4 v2 = ((const int4*)g_deg)[t * 4 + 2];
    int4 v3 = ((const int4*)g_deg)[t * 4 + 3];
    int vals[16] = {v0.x, v0.y, v0.z, v0.w, v1.x, v1.y, v1.z, v1.w,
                    v2.x, v2.y, v2.z, v2.w, v3.x, v3.y, v3.z, v3.w};
    int tot = 0;
#pragma unroll
    for (int i = 0; i < 16; i++) tot += vals[i];
    int inc = tot;
#pragma unroll
    for (int off = 1; off < 32; off <<= 1) {
        int n = __shfl_up_sync(0xFFFFFFFFu, inc, off);
        if (lane >= off) inc += n;
    }
    if (lane == 31) wsum[wid] = inc;
    __syncthreads();
    if (wid == 0) {
        int w = wsum[lane];
        int wi = w;
#pragma unroll
        for (int off = 1; off < 32; off <<= 1) {
            int n = __shfl_up_sync(0xFFFFFFFFu, wi, off);
            if (lane >= off) wi += n;
        }
        wsum[lane] = wi - w;
    }
    __syncthreads();
    int run = wsum[wid] + (inc - tot);
#pragma unroll
    for (int i = 0; i < 16; i++) { g_off[t * 16 + i] = run; run += vals[i]; }
    if (t == 1023) g_off[Nn] = run;
}

__global__ void scatter_kernel(const void* __restrict__ ei) {
    int e = blockIdx.x * blockDim.x + threadIdx.x;
    int is64 = g_is64;
    if (e < En) {
        int r = load_idx(ei, e, is64);
        int c = load_idx(ei, En + e, is64);
        if ((unsigned)r < Nn && (unsigned)c < Nn) {
            int p = atomicAdd(&g_cur[r], 1);
            g_csr[g_off[r] + p] = c;
        }
    }
}

// ============================================================
// Aggregation: per node, all 8 batches, gather-max - x -> fp16
// ============================================================
__global__ void __launch_bounds__(128) aggregate_kernel(const float* __restrict__ x) {
    const int i = blockIdx.x;
    const int c = threadIdx.x;
    const int s = g_off[i];
    const int e = g_off[i + 1];

    float m[Bn];
#pragma unroll
    for (int b = 0; b < Bn; b++) m[b] = -INFINITY;

    int k = s;
    for (; k + 4 <= e; k += 4) {
        int j0 = g_csr[k + 0], j1 = g_csr[k + 1], j2 = g_csr[k + 2], j3 = g_csr[k + 3];
        size_t o0 = (size_t)j0 * Cn + c, o1 = (size_t)j1 * Cn + c;
        size_t o2 = (size_t)j2 * Cn + c, o3 = (size_t)j3 * Cn + c;
#pragma unroll
        for (int b = 0; b < Bn; b++) {
            size_t xb = (size_t)b * Nn * Cn;
            float v0 = __ldg(&x[xb + o0]);
            float v1 = __ldg(&x[xb + o1]);
            float v2 = __ldg(&x[xb + o2]);
            float v3 = __ldg(&x[xb + o3]);
            m[b] = fmaxf(m[b], fmaxf(fmaxf(v0, v1), fmaxf(v2, v3)));
        }
    }
    for (; k < e; k++) {
        int j = g_csr[k];
        size_t o = (size_t)j * Cn + c;
#pragma unroll
        for (int b = 0; b < Bn; b++)
            m[b] = fmaxf(m[b], __ldg(&x[(size_t)b * Nn * Cn + o]));
    }

    const bool none = (s == e);
    const size_t obase = (size_t)i * Cn + c;
#pragma unroll
    for (int b = 0; b < Bn; b++) {
        size_t idx = (size_t)b * Nn * Cn + obase;
        float v = (none ? 0.0f : m[b]) - x[idx];
        g_ahi[idx] = __float2half_rn(v);
    }
}

// ============================================================
// GEMM via mma.sync fp16: (131072 x 128) @ (128 x 256) + bias + exact GELU
// out = Ah @ Wh  (rel_err ~3.5e-4, fp32 accumulate)
// CTA tile 128x256, 16 warps, warp tile 32x64.
// 2-stage cp.async pipeline over K halves (64 each).
// ============================================================
#define MMA_F16(d, a, b) \
    asm volatile("mma.sync.aligned.m16n8k16.row.col.f32.f16.f16.f32 " \
        "{%0,%1,%2,%3}, {%4,%5,%6,%7}, {%8,%9}, {%0,%1,%2,%3};" \
        : "+f"((d)[0]), "+f"((d)[1]), "+f"((d)[2]), "+f"((d)[3]) \
        : "r"((a)[0]), "r"((a)[1]), "r"((a)[2]), "r"((a)[3]), \
          "r"((b)[0]), "r"((b)[1]))

#define LDK   72                      // 64 + 8 pad (fp16)
#define A_ST  (128 * LDK)             // 9216 elements per stage
#define B_ST  (256 * LDK)             // 18432
#define OFF_AH 0
#define OFF_BH (2 * A_ST)
#define GEMM_SMEM ((2 * A_ST + 2 * B_ST) * 2)   // 110592 bytes

__device__ __forceinline__ float gelu_exact(float v) {
    return 0.5f * v * (1.0f + erff(v * 0.70710678118654752f));
}

__global__ void __launch_bounds__(512, 1) gemm_mma_kernel(const float* __restrict__ bias,
                                                          float* __restrict__ out) {
    extern __shared__ __align__(16) __half smem[];
    const int tid = threadIdx.x;
    const int wid = tid >> 5;
    const int lane = tid & 31;
    const size_t m0 = (size_t)blockIdx.x * 128;
    const int warp_m = wid & 3;    // 4 x 32 rows
    const int warp_n = wid >> 2;   // 4 x 64 cols

    // ---- async load both K-stages ----
#pragma unroll
    for (int s = 0; s < 2; s++) {
        const int ks = s * 64;
        // A: 1024 16B-chunks
#pragma unroll
        for (int it = 0; it < 2; it++) {
            int q = it * 512 + tid;
            int r = q >> 3;
            int c8 = (q & 7) * 8;
            uint32_t dh = smem_u32(&smem[OFF_AH + s * A_ST + r * LDK + c8]);
            CP_ASYNC16(dh, &g_ahi[(m0 + r) * Cn + ks + c8]);
        }
        // B: 2048 16B-chunks
#pragma unroll
        for (int it = 0; it < 4; it++) {
            int q = it * 512 + tid;
            int n = q >> 3;
            int c8 = (q & 7) * 8;
            uint32_t dh = smem_u32(&smem[OFF_BH + s * B_ST + n * LDK + c8]);
            CP_ASYNC16(dh, &g_wbh[(size_t)n * Cn + ks + c8]);
        }
        CP_COMMIT();
    }

    const int gr = lane >> 2;       // group row 0..7
    const int tg = lane & 3;        // thread in group

    float acc[2][8][4];
#pragma unroll
    for (int mf = 0; mf < 2; mf++)
#pragma unroll
        for (int nf = 0; nf < 8; nf++)
#pragma unroll
            for (int q = 0; q < 4; q++) acc[mf][nf][q] = 0.0f;

#pragma unroll
    for (int s = 0; s < 2; s++) {
        if (s == 0) { CP_WAIT(1); } else { CP_WAIT(0); }
        __syncthreads();
        const __half* Ah = smem + OFF_AH + s * A_ST;
        const __half* Bh = smem + OFF_BH + s * B_ST;

#pragma unroll
        for (int kc = 0; kc < 4; kc++) {
            const int kb = kc * 16 + tg * 2;
            uint32_t ah[2][4];
#pragma unroll
            for (int mf = 0; mf < 2; mf++) {
                int m = warp_m * 32 + mf * 16 + gr;
                ah[mf][0] = *(const uint32_t*)&Ah[m * LDK + kb];
                ah[mf][1] = *(const uint32_t*)&Ah[(m + 8) * LDK + kb];
                ah[mf][2] = *(const uint32_t*)&Ah[m * LDK + kb + 8];
                ah[mf][3] = *(const uint32_t*)&Ah[(m + 8) * LDK + kb + 8];
            }
#pragma unroll
            for (int nf = 0; nf < 8; nf++) {
                int n = warp_n * 64 + nf * 8 + gr;
                uint32_t bh[2];
                bh[0] = *(const uint32_t*)&Bh[n * LDK + kb];
                bh[1] = *(const uint32_t*)&Bh[n * LDK + kb + 8];
#pragma unroll
                for (int mf = 0; mf < 2; mf++) {
                    MMA_F16(acc[mf][nf], ah[mf], bh);
                }
            }
        }
        if (s == 0) __syncthreads();
    }

    // ---- epilogue: bias + exact GELU, direct float2 stores ----
#pragma unroll
    for (int nf = 0; nf < 8; nf++) {
        int col = warp_n * 64 + nf * 8 + tg * 2;
        float b0 = __ldg(&bias[col]), b1 = __ldg(&bias[col + 1]);
#pragma unroll
        for (int mf = 0; mf < 2; mf++) {
            size_t row = m0 + warp_m * 32 + mf * 16 + gr;
            float2 v0, v1;
            v0.x = gelu_exact(acc[mf][nf][0] + b0);
            v0.y = gelu_exact(acc[mf][nf][1] + b1);
            v1.x = gelu_exact(acc[mf][nf][2] + b0);
            v1.y = gelu_exact(acc[mf][nf][3] + b1);
            *(float2*)&out[row * OUTn + col]       = v0;
            *(float2*)&out[(row + 8) * OUTn + col] = v1;
        }
    }
}

// ============================================================
extern "C" void kernel_launch(void* const* d_in, const int* in_sizes, int n_in,
                              void* d_out, int out_size) {
    const float* x    = (const float*)d_in[0];
    const void*  ei   = d_in[1];
    const float* Wm   = (const float*)d_in[2];
    const float* bias = (const float*)d_in[3];
    float*       out  = (float*)d_out;

    cudaFuncSetAttribute(gemm_mma_kernel, cudaFuncAttributeMaxDynamicSharedMemorySize, GEMM_SMEM);

    detinit_kernel<<<(Cn * OUTn) / 256, 256>>>((const unsigned int*)ei, Wm);
    count_kernel<<<En / 256, 256>>>(ei);
    scan_kernel<<<1, 1024>>>();
    scatter_kernel<<<En / 256, 256>>>(ei);
    aggregate_kernel<<<Nn, 128>>>(x);
    gemm_mma_kernel<<<(Bn * Nn) / 128, 512, GEMM_SMEM>>>(bias, out);
}

// round 10
// speedup vs baseline: 2.2807x; 1.1788x over previous
#include <cuda_runtime.h>
#include <cuda_fp16.h>
#include <math.h>
#include <stdint.h>

#define Bn   8
#define Nn   16384
#define Cn   128
#define OUTn 256
#define En   262144

// ---- scratch (static device globals; no allocation allowed) ----
__device__ __align__(16) int g_deg[Nn];
__device__ int   g_off[Nn + 1];
__device__ int   g_cur[Nn];
__device__ int   g_csr[En];
__device__ int   g_is64;
__device__ __half g_x16[(size_t)Bn * Nn * Cn];   // 32 MB fp16 copy of x
__device__ __half g_ahi[(size_t)Bn * Nn * Cn];   // 32 MB aggr (fp16)
__device__ __half g_wbh[(size_t)OUTn * Cn];      // W^T fp16 [N][K]

__device__ __forceinline__ uint32_t smem_u32(const void* p) {
    return (uint32_t)__cvta_generic_to_shared(p);
}
#define CP_ASYNC16(dst_u32, src_ptr) \
    asm volatile("cp.async.cg.shared.global [%0], [%1], 16;" :: "r"(dst_u32), "l"(src_ptr))
#define CP_COMMIT() asm volatile("cp.async.commit_group;" ::: "memory")
#define CP_WAIT(n)  asm volatile("cp.async.wait_group %0;" :: "n"(n) : "memory")

// ============================================================
// detect dtype + init arrays + W^T fp16 convert, one kernel
// ============================================================
__global__ void detinit_kernel(const unsigned int* __restrict__ ei_raw,
                               const float* __restrict__ W) {
    int i = blockIdx.x * blockDim.x + threadIdx.x;   // 32768 threads
    if (i < Nn) { g_deg[i] = 0; g_cur[i] = 0; }
    if (i < Cn * OUTn) {
        int k = i >> 8;
        int n = i & 255;
        g_wbh[(size_t)n * Cn + k] = __float2half_rn(W[i]);
    }
    if (i == 0) {
        int hi_zero = 0;
        for (int q = 0; q < 256; q++)
            if (ei_raw[2 * q + 1] == 0) hi_zero++;
        g_is64 = (hi_zero >= 250) ? 1 : 0;
    }
}

__device__ __forceinline__ int load_idx(const void* ei, int pos, int is64) {
    if (is64) return (int)((const long long*)ei)[pos];
    return ((const int*)ei)[pos];
}

// ============================================================
// count (histogram) + x->fp16 convert, fused in one launch.
// bid < CNT_BLKS: count. bid >= CNT_BLKS: convert 8192 floats/block.
// ============================================================
#define CNT_BLKS  1024
#define CNV_BLKS  2048   // 16.78M elements / 8192

__global__ void countconv_kernel(const void* __restrict__ ei,
                                 const float* __restrict__ x) {
    const int bid = blockIdx.x;
    const int tid = threadIdx.x;
    if (bid < CNT_BLKS) {
        int e = bid * 256 + tid;
        int is64 = g_is64;
        if (e < En) {
            int r = load_idx(ei, e, is64);
            if ((unsigned)r < Nn) atomicAdd(&g_deg[r], 1);
        }
        return;
    }
    // convert: 8192 floats per block = 256 threads x 8 float4
    size_t base = (size_t)(bid - CNT_BLKS) * 8192 + tid * 4;
#pragma unroll
    for (int q = 0; q < 8; q++) {
        size_t idx = base + (size_t)q * 1024;
        float4 v = *(const float4*)&x[idx];
        __half2 h0 = __floats2half2_rn(v.x, v.y);
        __half2 h1 = __floats2half2_rn(v.z, v.w);
        *(uint2*)&g_x16[idx] = make_uint2(*(uint32_t*)&h0, *(uint32_t*)&h1);
    }
}

__global__ void __launch_bounds__(1024) scan_kernel() {
    __shared__ int wsum[32];
    int t = threadIdx.x, lane = t & 31, wid = t >> 5;
    int4 v0 = ((const int4*)g_deg)[t * 4 + 0];
    int4 v1 = ((const int4*)g_deg)[t * 4 + 1];
    int4 v2 = ((const int4*)g_deg)[t * 4 + 2];
    int4 v3 = ((const int4*)g_deg)[t * 4 + 3];
    int vals[16] = {v0.x, v0.y, v0.z, v0.w, v1.x, v1.y, v1.z, v1.w,
                    v2.x, v2.y, v2.z, v2.w, v3.x, v3.y, v3.z, v3.w};
    int tot = 0;
#pragma unroll
    for (int i = 0; i < 16; i++) tot += vals[i];
    int inc = tot;
#pragma unroll
    for (int off = 1; off < 32; off <<= 1) {
        int n = __shfl_up_sync(0xFFFFFFFFu, inc, off);
        if (lane >= off) inc += n;
    }
    if (lane == 31) wsum[wid] = inc;
    __syncthreads();
    if (wid == 0) {
        int w = wsum[lane];
        int wi = w;
#pragma unroll
        for (int off = 1; off < 32; off <<= 1) {
            int n = __shfl_up_sync(0xFFFFFFFFu, wi, off);
            if (lane >= off) wi += n;
        }
        wsum[lane] = wi - w;
    }
    __syncthreads();
    int run = wsum[wid] + (inc - tot);
#pragma unroll
    for (int i = 0; i < 16; i++) { g_off[t * 16 + i] = run; run += vals[i]; }
    if (t == 1023) g_off[Nn] = run;
}

__global__ void scatter_kernel(const void* __restrict__ ei) {
    int e = blockIdx.x * blockDim.x + threadIdx.x;
    int is64 = g_is64;
    if (e < En) {
        int r = load_idx(ei, e, is64);
        int c = load_idx(ei, En + e, is64);
        if ((unsigned)r < Nn && (unsigned)c < Nn) {
            int p = atomicAdd(&g_cur[r], 1);
            g_csr[g_off[r] + p] = c;
        }
    }
}

// ============================================================
// Aggregation: fp16 gather-max (monotone rounding => exact rn16 of max),
// subtract fp32 x, write fp16. 2 nodes/block, 64 threads/node (half2 lanes).
// ============================================================
__global__ void __launch_bounds__(128) aggregate_kernel(const float* __restrict__ x) {
    const int tid = threadIdx.x;
    const int node = blockIdx.x * 2 + (tid >> 6);
    const int c2 = tid & 63;               // half2 index: channels 2c2, 2c2+1
    const int s = g_off[node];
    const int e = g_off[node + 1];

    const __half NEGINF = __ushort_as_half(0xFC00);
    __half2 m[Bn];
#pragma unroll
    for (int b = 0; b < Bn; b++) m[b] = __halves2half2(NEGINF, NEGINF);

    int k = s;
    for (; k + 4 <= e; k += 4) {
        size_t o0 = ((size_t)g_csr[k + 0] * Cn >> 1) + c2;
        size_t o1 = ((size_t)g_csr[k + 1] * Cn >> 1) + c2;
        size_t o2 = ((size_t)g_csr[k + 2] * Cn >> 1) + c2;
        size_t o3 = ((size_t)g_csr[k + 3] * Cn >> 1) + c2;
        const __half2* xp = (const __half2*)g_x16;
#pragma unroll
        for (int b = 0; b < Bn; b++) {
            size_t xb = (size_t)b * Nn * (Cn / 2);
            __half2 v0 = xp[xb + o0];
            __half2 v1 = xp[xb + o1];
            __half2 v2 = xp[xb + o2];
            __half2 v3 = xp[xb + o3];
            m[b] = __hmax2(m[b], __hmax2(__hmax2(v0, v1), __hmax2(v2, v3)));
        }
    }
    for (; k < e; k++) {
        size_t o = ((size_t)g_csr[k] * Cn >> 1) + c2;
        const __half2* xp = (const __half2*)g_x16;
#pragma unroll
        for (int b = 0; b < Bn; b++)
            m[b] = __hmax2(m[b], xp[(size_t)b * Nn * (Cn / 2) + o]);
    }

    const bool none = (s == e);
    const size_t obase = (size_t)node * Cn + c2 * 2;
#pragma unroll
    for (int b = 0; b < Bn; b++) {
        size_t idx = (size_t)b * Nn * Cn + obase;
        float2 xv = *(const float2*)&x[idx];
        float m0 = none ? 0.0f : __half2float(__low2half(m[b]));
        float m1 = none ? 0.0f : __half2float(__high2half(m[b]));
        __half2 r = __floats2half2_rn(m0 - xv.x, m1 - xv.y);
        *(uint32_t*)&g_ahi[idx] = *(uint32_t*)&r;
    }
}

// ============================================================
// GEMM via mma.sync fp16: (131072 x 128) @ (128 x 256) + bias + exact GELU
// CTA tile 128x256, 16 warps, warp tile 32x64, 2-stage cp.async over K.
// ============================================================
#define MMA_F16(d, a, b) \
    asm volatile("mma.sync.aligned.m16n8k16.row.col.f32.f16.f16.f32 " \
        "{%0,%1,%2,%3}, {%4,%5,%6,%7}, {%8,%9}, {%0,%1,%2,%3};" \
        : "+f"((d)[0]), "+f"((d)[1]), "+f"((d)[2]), "+f"((d)[3]) \
        : "r"((a)[0]), "r"((a)[1]), "r"((a)[2]), "r"((a)[3]), \
          "r"((b)[0]), "r"((b)[1]))

#define LDK   72
#define A_ST  (128 * LDK)
#define B_ST  (256 * LDK)
#define OFF_AH 0
#define OFF_BH (2 * A_ST)
#define GEMM_SMEM ((2 * A_ST + 2 * B_ST) * 2)   // 110592 bytes

__device__ __forceinline__ float gelu_exact(float v) {
    return 0.5f * v * (1.0f + erff(v * 0.70710678118654752f));
}

__global__ void __launch_bounds__(512, 1) gemm_mma_kernel(const float* __restrict__ bias,
                                                          float* __restrict__ out) {
    extern __shared__ __align__(16) __half smem[];
    const int tid = threadIdx.x;
    const int wid = tid >> 5;
    const int lane = tid & 31;
    const size_t m0 = (size_t)blockIdx.x * 128;
    const int warp_m = wid & 3;
    const int warp_n = wid >> 2;

#pragma unroll
    for (int s = 0; s < 2; s++) {
        const int ks = s * 64;
#pragma unroll
        for (int it = 0; it < 2; it++) {
            int q = it * 512 + tid;
            int r = q >> 3;
            int c8 = (q & 7) * 8;
            uint32_t dh = smem_u32(&smem[OFF_AH + s * A_ST + r * LDK + c8]);
            CP_ASYNC16(dh, &g_ahi[(m0 + r) * Cn + ks + c8]);
        }
#pragma unroll
        for (int it = 0; it < 4; it++) {
            int q = it * 512 + tid;
            int n = q >> 3;
            int c8 = (q & 7) * 8;
            uint32_t dh = smem_u32(&smem[OFF_BH + s * B_ST + n * LDK + c8]);
            CP_ASYNC16(dh, &g_wbh[(size_t)n * Cn + ks + c8]);
        }
        CP_COMMIT();
    }

    const int gr = lane >> 2;
    const int tg = lane & 3;

    float acc[2][8][4];
#pragma unroll
    for (int mf = 0; mf < 2; mf++)
#pragma unroll
        for (int nf = 0; nf < 8; nf++)
#pragma unroll
            for (int q = 0; q < 4; q++) acc[mf][nf][q] = 0.0f;

#pragma unroll
    for (int s = 0; s < 2; s++) {
        if (s == 0) { CP_WAIT(1); } else { CP_WAIT(0); }
        __syncthreads();
        const __half* Ah = smem + OFF_AH + s * A_ST;
        const __half* Bh = smem + OFF_BH + s * B_ST;

#pragma unroll
        for (int kc = 0; kc < 4; kc++) {
            const int kb = kc * 16 + tg * 2;
            uint32_t ah[2][4];
#pragma unroll
            for (int mf = 0; mf < 2; mf++) {
                int m = warp_m * 32 + mf * 16 + gr;
                ah[mf][0] = *(const uint32_t*)&Ah[m * LDK + kb];
                ah[mf][1] = *(const uint32_t*)&Ah[(m + 8) * LDK + kb];
                ah[mf][2] = *(const uint32_t*)&Ah[m * LDK + kb + 8];
                ah[mf][3] = *(const uint32_t*)&Ah[(m + 8) * LDK + kb + 8];
            }
#pragma unroll
            for (int nf = 0; nf < 8; nf++) {
                int n = warp_n * 64 + nf * 8 + gr;
                uint32_t bh[2];
                bh[0] = *(const uint32_t*)&Bh[n * LDK + kb];
                bh[1] = *(const uint32_t*)&Bh[n * LDK + kb + 8];
#pragma unroll
                for (int mf = 0; mf < 2; mf++) {
                    MMA_F16(acc[mf][nf], ah[mf], bh);
                }
            }
        }
        if (s == 0) __syncthreads();
    }

#pragma unroll
    for (int nf = 0; nf < 8; nf++) {
        int col = warp_n * 64 + nf * 8 + tg * 2;
        float b0 = __ldg(&bias[col]), b1 = __ldg(&bias[col + 1]);
#pragma unroll
        for (int mf = 0; mf < 2; mf++) {
            size_t row = m0 + warp_m * 32 + mf * 16 + gr;
            float2 v0, v1;
            v0.x = gelu_exact(acc[mf][nf][0] + b0);
            v0.y = gelu_exact(acc[mf][nf][1] + b1);
            v1.x = gelu_exact(acc[mf][nf][2] + b0);
            v1.y = gelu_exact(acc[mf][nf][3] + b1);
            *(float2*)&out[row * OUTn + col]       = v0;
            *(float2*)&out[(row + 8) * OUTn + col] = v1;
        }
    }
}

// ============================================================
extern "C" void kernel_launch(void* const* d_in, const int* in_sizes, int n_in,
                              void* d_out, int out_size) {
    const float* x    = (const float*)d_in[0];
    const void*  ei   = d_in[1];
    const float* Wm   = (const float*)d_in[2];
    const float* bias = (const float*)d_in[3];
    float*       out  = (float*)d_out;

    cudaFuncSetAttribute(gemm_mma_kernel, cudaFuncAttributeMaxDynamicSharedMemorySize, GEMM_SMEM);

    detinit_kernel<<<(Cn * OUTn) / 256, 256>>>((const unsigned int*)ei, Wm);
    countconv_kernel<<<CNT_BLKS + CNV_BLKS, 256>>>(ei, x);
    scan_kernel<<<1, 1024>>>();
    scatter_kernel<<<En / 256, 256>>>(ei);
    aggregate_kernel<<<Nn / 2, 128>>>(x);
    gemm_mma_kernel<<<(Bn * Nn) / 128, 512, GEMM_SMEM>>>(bias, out);
}

// round 11
// speedup vs baseline: 2.3443x; 1.0279x over previous
#include <cuda_runtime.h>
#include <cuda_fp16.h>
#include <math.h>
#include <stdint.h>

#define Bn   8
#define Nn   16384
#define Cn   128
#define OUTn 256
#define En   262144

// ---- scratch (static device globals; no allocation allowed) ----
__device__ __align__(16) int g_deg[Nn];
__device__ int   g_off[Nn + 1];
__device__ int   g_cur[Nn];
__device__ int   g_csr[En];
__device__ int   g_is64;
__device__ __half g_x16[(size_t)Bn * Nn * Cn];   // 32 MB fp16 copy of x
__device__ __half g_ahi[(size_t)Bn * Nn * Cn];   // 32 MB aggr (fp16)
__device__ __half g_wbh[(size_t)OUTn * Cn];      // W^T fp16 [N][K]

__device__ __forceinline__ uint32_t smem_u32(const void* p) {
    return (uint32_t)__cvta_generic_to_shared(p);
}
#define CP_ASYNC16(dst_u32, src_ptr) \
    asm volatile("cp.async.cg.shared.global [%0], [%1], 16;" :: "r"(dst_u32), "l"(src_ptr))
#define CP_COMMIT() asm volatile("cp.async.commit_group;" ::: "memory")
#define CP_WAIT(n)  asm volatile("cp.async.wait_group %0;" :: "n"(n) : "memory")

// ============================================================
// detect dtype + init arrays + W^T fp16 convert, one kernel
// ============================================================
__global__ void detinit_kernel(const unsigned int* __restrict__ ei_raw,
                               const float* __restrict__ W) {
    int i = blockIdx.x * blockDim.x + threadIdx.x;   // 32768 threads
    if (i < Nn) { g_deg[i] = 0; g_cur[i] = 0; }
    if (i < Cn * OUTn) {
        int k = i >> 8;
        int n = i & 255;
        g_wbh[(size_t)n * Cn + k] = __float2half_rn(W[i]);
    }
    if (i == 0) {
        int hi_zero = 0;
        for (int q = 0; q < 256; q++)
            if (ei_raw[2 * q + 1] == 0) hi_zero++;
        g_is64 = (hi_zero >= 250) ? 1 : 0;
    }
}

__device__ __forceinline__ int load_idx(const void* ei, int pos, int is64) {
    if (is64) return (int)((const long long*)ei)[pos];
    return ((const int*)ei)[pos];
}

// ============================================================
// count (histogram) + x->fp16 convert, fused in one launch.
// ============================================================
#define CNT_BLKS  1024
#define CNV_BLKS  2048   // 16.78M elements / 8192

__global__ void countconv_kernel(const void* __restrict__ ei,
                                 const float* __restrict__ x) {
    const int bid = blockIdx.x;
    const int tid = threadIdx.x;
    if (bid < CNT_BLKS) {
        int e = bid * 256 + tid;
        int is64 = g_is64;
        if (e < En) {
            int r = load_idx(ei, e, is64);
            if ((unsigned)r < Nn) atomicAdd(&g_deg[r], 1);
        }
        return;
    }
    size_t base = (size_t)(bid - CNT_BLKS) * 8192 + tid * 4;
#pragma unroll
    for (int q = 0; q < 8; q++) {
        size_t idx = base + (size_t)q * 1024;
        float4 v = *(const float4*)&x[idx];
        __half2 h0 = __floats2half2_rn(v.x, v.y);
        __half2 h1 = __floats2half2_rn(v.z, v.w);
        *(uint2*)&g_x16[idx] = make_uint2(*(uint32_t*)&h0, *(uint32_t*)&h1);
    }
}

__global__ void __launch_bounds__(1024) scan_kernel() {
    __shared__ int wsum[32];
    int t = threadIdx.x, lane = t & 31, wid = t >> 5;
    int4 v0 = ((const int4*)g_deg)[t * 4 + 0];
    int4 v1 = ((const int4*)g_deg)[t * 4 + 1];
    int4 v2 = ((const int4*)g_deg)[t * 4 + 2];
    int4 v3 = ((const int4*)g_deg)[t * 4 + 3];
    int vals[16] = {v0.x, v0.y, v0.z, v0.w, v1.x, v1.y, v1.z, v1.w,
                    v2.x, v2.y, v2.z, v2.w, v3.x, v3.y, v3.z, v3.w};
    int tot = 0;
#pragma unroll
    for (int i = 0; i < 16; i++) tot += vals[i];
    int inc = tot;
#pragma unroll
    for (int off = 1; off < 32; off <<= 1) {
        int n = __shfl_up_sync(0xFFFFFFFFu, inc, off);
        if (lane >= off) inc += n;
    }
    if (lane == 31) wsum[wid] = inc;
    __syncthreads();
    if (wid == 0) {
        int w = wsum[lane];
        int wi = w;
#pragma unroll
        for (int off = 1; off < 32; off <<= 1) {
            int n = __shfl_up_sync(0xFFFFFFFFu, wi, off);
            if (lane >= off) wi += n;
        }
        wsum[lane] = wi - w;
    }
    __syncthreads();
    int run = wsum[wid] + (inc - tot);
#pragma unroll
    for (int i = 0; i < 16; i++) { g_off[t * 16 + i] = run; run += vals[i]; }
    if (t == 1023) g_off[Nn] = run;
}

__global__ void scatter_kernel(const void* __restrict__ ei) {
    int e = blockIdx.x * blockDim.x + threadIdx.x;
    int is64 = g_is64;
    if (e < En) {
        int r = load_idx(ei, e, is64);
        int c = load_idx(ei, En + e, is64);
        if ((unsigned)r < Nn && (unsigned)c < Nn) {
            int p = atomicAdd(&g_cur[r], 1);
            g_csr[g_off[r] + p] = c;
        }
    }
}

// ============================================================
// Aggregation: fp16 gather-max, subtract fp32 x, write fp16.
// ============================================================
__global__ void __launch_bounds__(128) aggregate_kernel(const float* __restrict__ x) {
    const int tid = threadIdx.x;
    const int node = blockIdx.x * 2 + (tid >> 6);
    const int c2 = tid & 63;
    const int s = g_off[node];
    const int e = g_off[node + 1];

    const __half NEGINF = __ushort_as_half(0xFC00);
    __half2 m[Bn];
#pragma unroll
    for (int b = 0; b < Bn; b++) m[b] = __halves2half2(NEGINF, NEGINF);

    int k = s;
    for (; k + 4 <= e; k += 4) {
        size_t o0 = ((size_t)g_csr[k + 0] * Cn >> 1) + c2;
        size_t o1 = ((size_t)g_csr[k + 1] * Cn >> 1) + c2;
        size_t o2 = ((size_t)g_csr[k + 2] * Cn >> 1) + c2;
        size_t o3 = ((size_t)g_csr[k + 3] * Cn >> 1) + c2;
        const __half2* xp = (const __half2*)g_x16;
#pragma unroll
        for (int b = 0; b < Bn; b++) {
            size_t xb = (size_t)b * Nn * (Cn / 2);
            __half2 v0 = xp[xb + o0];
            __half2 v1 = xp[xb + o1];
            __half2 v2 = xp[xb + o2];
            __half2 v3 = xp[xb + o3];
            m[b] = __hmax2(m[b], __hmax2(__hmax2(v0, v1), __hmax2(v2, v3)));
        }
    }
    for (; k < e; k++) {
        size_t o = ((size_t)g_csr[k] * Cn >> 1) + c2;
        const __half2* xp = (const __half2*)g_x16;
#pragma unroll
        for (int b = 0; b < Bn; b++)
            m[b] = __hmax2(m[b], xp[(size_t)b * Nn * (Cn / 2) + o]);
    }

    const bool none = (s == e);
    const size_t obase = (size_t)node * Cn + c2 * 2;
#pragma unroll
    for (int b = 0; b < Bn; b++) {
        size_t idx = (size_t)b * Nn * Cn + obase;
        float2 xv = *(const float2*)&x[idx];
        float m0 = none ? 0.0f : __half2float(__low2half(m[b]));
        float m1 = none ? 0.0f : __half2float(__high2half(m[b]));
        __half2 r = __floats2half2_rn(m0 - xv.x, m1 - xv.y);
        *(uint32_t*)&g_ahi[idx] = *(uint32_t*)&r;
    }
}

// ============================================================
// GEMM via mma.sync fp16: (131072 x 128) @ (128 x 256) + bias + exact GELU
// CTA tile 128x128, 8 warps, warp tile 32x64, 2 CTAs/SM,
// 2-stage cp.async over K halves.
// ============================================================
#define MMA_F16(d, a, b) \
    asm volatile("mma.sync.aligned.m16n8k16.row.col.f32.f16.f16.f32 " \
        "{%0,%1,%2,%3}, {%4,%5,%6,%7}, {%8,%9}, {%0,%1,%2,%3};" \
        : "+f"((d)[0]), "+f"((d)[1]), "+f"((d)[2]), "+f"((d)[3]) \
        : "r"((a)[0]), "r"((a)[1]), "r"((a)[2]), "r"((a)[3]), \
          "r"((b)[0]), "r"((b)[1]))

#define LDK   72                      // 64 + 8 pad (fp16)
#define A_ST  (128 * LDK)             // 9216 elements per stage
#define B_ST  (128 * LDK)             // 9216
#define OFF_AH 0
#define OFF_BH (2 * A_ST)
#define GEMM_SMEM ((2 * A_ST + 2 * B_ST) * 2)   // 73728 bytes

__device__ __forceinline__ float gelu_exact(float v) {
    return 0.5f * v * (1.0f + erff(v * 0.70710678118654752f));
}

__global__ void __launch_bounds__(256, 2) gemm_mma_kernel(const float* __restrict__ bias,
                                                          float* __restrict__ out) {
    extern __shared__ __align__(16) __half smem[];
    const int tid = threadIdx.x;
    const int wid = tid >> 5;
    const int lane = tid & 31;
    const size_t m0 = (size_t)blockIdx.x * 128;
    const int n0 = blockIdx.y * 128;
    const int warp_m = wid & 3;    // 4 x 32 rows
    const int warp_n = wid >> 2;   // 2 x 64 cols

    // ---- async load both K-stages ----
#pragma unroll
    for (int s = 0; s < 2; s++) {
        const int ks = s * 64;
        // A: 1024 16B-chunks
#pragma unroll
        for (int it = 0; it < 4; it++) {
            int q = it * 256 + tid;
            int r = q >> 3;
            int c8 = (q & 7) * 8;
            uint32_t dh = smem_u32(&smem[OFF_AH + s * A_ST + r * LDK + c8]);
            CP_ASYNC16(dh, &g_ahi[(m0 + r) * Cn + ks + c8]);
        }
        // B: 1024 16B-chunks
#pragma unroll
        for (int it = 0; it < 4; it++) {
            int q = it * 256 + tid;
            int n = q >> 3;
            int c8 = (q & 7) * 8;
            uint32_t dh = smem_u32(&smem[OFF_BH + s * B_ST + n * LDK + c8]);
            CP_ASYNC16(dh, &g_wbh[(size_t)(n0 + n) * Cn + ks + c8]);
        }
        CP_COMMIT();
    }

    const int gr = lane >> 2;
    const int tg = lane & 3;

    float acc[2][8][4];
#pragma unroll
    for (int mf = 0; mf < 2; mf++)
#pragma unroll
        for (int nf = 0; nf < 8; nf++)
#pragma unroll
            for (int q = 0; q < 4; q++) acc[mf][nf][q] = 0.0f;

#pragma unroll
    for (int s = 0; s < 2; s++) {
        if (s == 0) { CP_WAIT(1); } else { CP_WAIT(0); }
        __syncthreads();
        const __half* Ah = smem + OFF_AH + s * A_ST;
        const __half* Bh = smem + OFF_BH + s * B_ST;

#pragma unroll
        for (int kc = 0; kc < 4; kc++) {
            const int kb = kc * 16 + tg * 2;
            uint32_t ah[2][4];
#pragma unroll
            for (int mf = 0; mf < 2; mf++) {
                int m = warp_m * 32 + mf * 16 + gr;
                ah[mf][0] = *(const uint32_t*)&Ah[m * LDK + kb];
                ah[mf][1] = *(const uint32_t*)&Ah[(m + 8) * LDK + kb];
                ah[mf][2] = *(const uint32_t*)&Ah[m * LDK + kb + 8];
                ah[mf][3] = *(const uint32_t*)&Ah[(m + 8) * LDK + kb + 8];
            }
#pragma unroll
            for (int nf = 0; nf < 8; nf++) {
                int n = warp_n * 64 + nf * 8 + gr;
                uint32_t bh[2];
                bh[0] = *(const uint32_t*)&Bh[n * LDK + kb];
                bh[1] = *(const uint32_t*)&Bh[n * LDK + kb + 8];
#pragma unroll
                for (int mf = 0; mf < 2; mf++) {
                    MMA_F16(acc[mf][nf], ah[mf], bh);
                }
            }
        }
        if (s == 0) __syncthreads();
    }

    // ---- epilogue: bias + exact GELU, direct float2 stores ----
#pragma unroll
    for (int nf = 0; nf < 8; nf++) {
        int col = n0 + warp_n * 64 + nf * 8 + tg * 2;
        float b0 = __ldg(&bias[col]), b1 = __ldg(&bias[col + 1]);
#pragma unroll
        for (int mf = 0; mf < 2; mf++) {
            size_t row = m0 + warp_m * 32 + mf * 16 + gr;
            float2 v0, v1;
            v0.x = gelu_exact(acc[mf][nf][0] + b0);
            v0.y = gelu_exact(acc[mf][nf][1] + b1);
            v1.x = gelu_exact(acc[mf][nf][2] + b0);
            v1.y = gelu_exact(acc[mf][nf][3] + b1);
            *(float2*)&out[row * OUTn + col]       = v0;
            *(float2*)&out[(row + 8) * OUTn + col] = v1;
        }
    }
}

// ============================================================
extern "C" void kernel_launch(void* const* d_in, const int* in_sizes, int n_in,
                              void* d_out, int out_size) {
    const float* x    = (const float*)d_in[0];
    const void*  ei   = d_in[1];
    const float* Wm   = (const float*)d_in[2];
    const float* bias = (const float*)d_in[3];
    float*       out  = (float*)d_out;

    cudaFuncSetAttribute(gemm_mma_kernel, cudaFuncAttributeMaxDynamicSharedMemorySize, GEMM_SMEM);

    detinit_kernel<<<(Cn * OUTn) / 256, 256>>>((const unsigned int*)ei, Wm);
    countconv_kernel<<<CNT_BLKS + CNV_BLKS, 256>>>(ei, x);
    scan_kernel<<<1, 1024>>>();
    scatter_kernel<<<En / 256, 256>>>(ei);
    aggregate_kernel<<<Nn / 2, 128>>>(x);
    dim3 g((Bn * Nn) / 128, OUTn / 128);
    gemm_mma_kernel<<<g, 256, GEMM_SMEM>>>(bias, out);
}